// round 5
// baseline (speedup 1.0000x reference)
#include <cuda_runtime.h>
#include <cstdint>

#define NN 100000
#define EE 1600000
#define FD 128
#define BB 50
#define PP 2000
#define CC 10
#define KINV (1.0f/30.0f)
#define NBLK ((NN + 255) / 256)   // 391

// Scratch (static device globals — no allocation at launch time).
static __device__ float g_tmp[NN*FD];        // (A@W) * inv[row]  (gather source)
static __device__ float g_h1[NN*FD];         // relu(layer-1 output)
static __device__ float g_h2[NN*FD];         // relu(layer-2 output)
static __device__ float g_inv[NN];           // rsqrt(deg+1)
static __device__ float g_part[BB*8*FD];     // pooling partials
static __device__ int   g_cnt[NN];           // histogram (= degree)
static __device__ int   g_cur[NN];           // fill cursors
static __device__ int   g_off[NN];           // CSR row offsets (exclusive scan)
static __device__ int   g_src[EE];           // CSR src indices (grouped by dst)
static __device__ int   g_blksum[NBLK];
static __device__ int   g_blkoff[NBLK];

// ---------------- CSR-by-dst construction ----------------

__global__ void k_zero() {
    int i = blockIdx.x*blockDim.x + threadIdx.x;
    if (i < NN) { g_cnt[i] = 0; g_cur[i] = 0; }
}

__global__ void k_hist(const int* __restrict__ ei, int E) {
    int e = blockIdx.x*blockDim.x + threadIdx.x;
    if (e < E) atomicAdd(&g_cnt[ei[E + e]], 1);
}

__global__ void k_scan_block() {
    __shared__ int sh[256];
    int t = threadIdx.x;
    int i = blockIdx.x*256 + t;
    int v = (i < NN) ? g_cnt[i] : 0;
    sh[t] = v;
    __syncthreads();
    #pragma unroll
    for (int d = 1; d < 256; d <<= 1) {
        int x = (t >= d) ? sh[t-d] : 0;
        __syncthreads();
        sh[t] += x;
        __syncthreads();
    }
    if (i < NN) {
        g_off[i] = sh[t] - v;
        g_inv[i] = rsqrtf((float)v + 1.0f);
    }
    if (t == 255) g_blksum[blockIdx.x] = sh[255];
}

__global__ void k_scan_top() {
    __shared__ int sh[512];
    int t = threadIdx.x;
    int v = (t < NBLK) ? g_blksum[t] : 0;
    sh[t] = v;
    __syncthreads();
    #pragma unroll
    for (int d = 1; d < 512; d <<= 1) {
        int x = (t >= d) ? sh[t-d] : 0;
        __syncthreads();
        sh[t] += x;
        __syncthreads();
    }
    if (t < NBLK) g_blkoff[t] = sh[t] - v;
}

__global__ void k_scan_add() {
    int i = blockIdx.x*256 + threadIdx.x;
    if (i < NN) g_off[i] += g_blkoff[blockIdx.x];
}

__global__ void k_fill(const int* __restrict__ ei, int E) {
    int e = blockIdx.x*blockDim.x + threadIdx.x;
    if (e < E) {
        int s = ei[e];
        int d = ei[E + e];
        int pos = g_off[d] + atomicAdd(&g_cur[d], 1);
        g_src[pos] = s;
    }
}

// ---------------- tensor-core 3xTF32 GEMM: tmp' = (A @ W) * inv[row] ----------------

// cvt.rna.tf32.f32 requires a .b32 destination register (round-4 ptxas fix).
__device__ __forceinline__ uint32_t tf32_rna(float x) {
    uint32_t y;
    asm("cvt.rna.tf32.f32 %0, %1;" : "=r"(y) : "f"(x));
    return y;
}

__device__ __forceinline__ void mma_tf32(float* d, const uint32_t* a, const uint32_t* b) {
    asm volatile(
        "mma.sync.aligned.m16n8k8.row.col.f32.tf32.tf32.f32 "
        "{%0,%1,%2,%3}, {%4,%5,%6,%7}, {%8,%9}, {%0,%1,%2,%3};"
        : "+f"(d[0]), "+f"(d[1]), "+f"(d[2]), "+f"(d[3])
        : "r"(a[0]), "r"(a[1]), "r"(a[2]), "r"(a[3]), "r"(b[0]), "r"(b[1]));
}

// Block: 128 rows x 128 cols. 8 warps: warp_m = wid&1 (64-row half),
// warp_n = wid>>1 (32-col quarter). 3xTF32: acc += Ah*Bh + Al*Bh + Ah*Bl.
template<int LAYER>
__global__ void __launch_bounds__(256, 1)
k_gemm_tc(const float* __restrict__ X, const float* __restrict__ W) {
    const float* A = (LAYER == 1) ? X : (const float*)g_h1;

    // [k][·] layout, pitch 136 floats (mod 32 = 8) -> conflict-free frag LDS
    __shared__ float Ah[16][136], Al[16][136];
    __shared__ float Bh[16][136], Bl[16][136];

    const int tid  = threadIdx.x;
    const int row0 = blockIdx.x * 128;
    const int wid  = tid >> 5;
    const int lane = tid & 31;
    const int gid  = lane >> 2;        // 0..7
    const int t4   = lane & 3;         // 0..3
    const int m0b  = (wid & 1) * 64;
    const int n0b  = (wid >> 1) * 32;

    float acc[4][4][4];
    #pragma unroll
    for (int mt = 0; mt < 4; mt++)
        #pragma unroll
        for (int nt = 0; nt < 4; nt++)
            #pragma unroll
            for (int r = 0; r < 4; r++) acc[mt][nt][r] = 0.f;

    // A-chunk load mapping
    const int a_row  = tid & 127;
    const int a_half = tid >> 7;       // k offset half*8
    const int a_grow = row0 + a_row;
    // W-chunk load mapping
    const int w_k  = tid >> 4;         // 0..15
    const int w_n8 = (tid & 15) * 8;

    for (int k0 = 0; k0 < FD; k0 += 16) {
        // --- load & split A[row0..+127][k0..+15] into Ah/Al ([k][row]) ---
        float4 v0 = make_float4(0.f,0.f,0.f,0.f), v1 = v0;
        if (a_grow < NN) {
            const float* p = A + (size_t)a_grow*FD + k0 + a_half*8;
            v0 = *reinterpret_cast<const float4*>(p);
            v1 = *reinterpret_cast<const float4*>(p + 4);
        }
        {
            float e[8] = {v0.x,v0.y,v0.z,v0.w,v1.x,v1.y,v1.z,v1.w};
            #pragma unroll
            for (int j = 0; j < 8; j++) {
                uint32_t hb = tf32_rna(e[j]);
                float hi = __uint_as_float(hb);
                Ah[a_half*8 + j][a_row] = hi;
                Al[a_half*8 + j][a_row] = __uint_as_float(tf32_rna(e[j] - hi));
            }
        }
        // --- load & split W[k0..+15][0..127] into Bh/Bl ([k][n]) ---
        {
            const float* p = W + (size_t)(k0 + w_k)*FD + w_n8;
            float4 u0 = *reinterpret_cast<const float4*>(p);
            float4 u1 = *reinterpret_cast<const float4*>(p + 4);
            float e[8] = {u0.x,u0.y,u0.z,u0.w,u1.x,u1.y,u1.z,u1.w};
            float hh[8], ll[8];
            #pragma unroll
            for (int j = 0; j < 8; j++) {
                uint32_t hb = tf32_rna(e[j]);
                hh[j] = __uint_as_float(hb);
                ll[j] = __uint_as_float(tf32_rna(e[j] - hh[j]));
            }
            *reinterpret_cast<float4*>(&Bh[w_k][w_n8])     = make_float4(hh[0],hh[1],hh[2],hh[3]);
            *reinterpret_cast<float4*>(&Bh[w_k][w_n8 + 4]) = make_float4(hh[4],hh[5],hh[6],hh[7]);
            *reinterpret_cast<float4*>(&Bl[w_k][w_n8])     = make_float4(ll[0],ll[1],ll[2],ll[3]);
            *reinterpret_cast<float4*>(&Bl[w_k][w_n8 + 4]) = make_float4(ll[4],ll[5],ll[6],ll[7]);
        }
        __syncthreads();

        #pragma unroll
        for (int ks = 0; ks < 16; ks += 8) {
            uint32_t bh[4][2], bl[4][2];
            #pragma unroll
            for (int nt = 0; nt < 4; nt++) {
                int n = n0b + nt*8 + gid;
                bh[nt][0] = __float_as_uint(Bh[ks + t4][n]);
                bh[nt][1] = __float_as_uint(Bh[ks + t4 + 4][n]);
                bl[nt][0] = __float_as_uint(Bl[ks + t4][n]);
                bl[nt][1] = __float_as_uint(Bl[ks + t4 + 4][n]);
            }
            #pragma unroll
            for (int mt = 0; mt < 4; mt++) {
                int m = m0b + mt*16 + gid;
                uint32_t ah[4], al[4];
                ah[0] = __float_as_uint(Ah[ks + t4][m]);
                ah[1] = __float_as_uint(Ah[ks + t4][m + 8]);
                ah[2] = __float_as_uint(Ah[ks + t4 + 4][m]);
                ah[3] = __float_as_uint(Ah[ks + t4 + 4][m + 8]);
                al[0] = __float_as_uint(Al[ks + t4][m]);
                al[1] = __float_as_uint(Al[ks + t4][m + 8]);
                al[2] = __float_as_uint(Al[ks + t4 + 4][m]);
                al[3] = __float_as_uint(Al[ks + t4 + 4][m + 8]);
                #pragma unroll
                for (int nt = 0; nt < 4; nt++) {
                    mma_tf32(acc[mt][nt], ah, bh[nt]);   // hi*hi
                    mma_tf32(acc[mt][nt], al, bh[nt]);   // lo*hi
                    mma_tf32(acc[mt][nt], ah, bl[nt]);   // hi*lo
                }
            }
        }
        __syncthreads();
    }

    // Epilogue: scale rows by inv and store to g_tmp
    #pragma unroll
    for (int mt = 0; mt < 4; mt++) {
        int r0 = row0 + m0b + mt*16 + gid;
        int r1 = r0 + 8;
        float iv0 = (r0 < NN) ? g_inv[r0] : 0.f;
        float iv1 = (r1 < NN) ? g_inv[r1] : 0.f;
        #pragma unroll
        for (int nt = 0; nt < 4; nt++) {
            int c = n0b + nt*8 + t4*2;
            if (r0 < NN) {
                float2 o = make_float2(acc[mt][nt][0]*iv0, acc[mt][nt][1]*iv0);
                *reinterpret_cast<float2*>(g_tmp + (size_t)r0*FD + c) = o;
            }
            if (r1 < NN) {
                float2 o = make_float2(acc[mt][nt][2]*iv1, acc[mt][nt][3]*iv1);
                *reinterpret_cast<float2*>(g_tmp + (size_t)r1*FD + c) = o;
            }
        }
    }
}

// ---------------- CSR gather: one warp per dst node ----------------
// H[dst] = relu( inv[dst] * (tmp'[dst] + sum_{src} tmp'[src]) + b )

template<int LAYER>
__global__ void __launch_bounds__(256)
k_gather(const float* __restrict__ bias) {
    int node = blockIdx.x*8 + (threadIdx.x >> 5);
    if (node >= NN) return;
    float* H = (LAYER == 1) ? g_h1 : g_h2;

    const int lane  = threadIdx.x & 31;
    const int start = g_off[node];
    const int deg   = g_cnt[node];

    float4 acc0 = *reinterpret_cast<const float4*>(g_tmp + (size_t)node*FD + lane*4);
    float4 acc1 = make_float4(0.f, 0.f, 0.f, 0.f);

    for (int base = 0; base < deg; base += 32) {
        int n = deg - base; if (n > 32) n = 32;
        int s = (base + lane < deg) ? g_src[start + base + lane] : 0;
        int j = 0;
        for (; j + 1 < n; j += 2) {
            int s0 = __shfl_sync(0xffffffff, s, j);
            int s1 = __shfl_sync(0xffffffff, s, j+1);
            float4 v0 = *reinterpret_cast<const float4*>(g_tmp + (size_t)s0*FD + lane*4);
            float4 v1 = *reinterpret_cast<const float4*>(g_tmp + (size_t)s1*FD + lane*4);
            acc0.x += v0.x; acc0.y += v0.y; acc0.z += v0.z; acc0.w += v0.w;
            acc1.x += v1.x; acc1.y += v1.y; acc1.z += v1.z; acc1.w += v1.w;
        }
        if (j < n) {
            int s0 = __shfl_sync(0xffffffff, s, j);
            float4 v0 = *reinterpret_cast<const float4*>(g_tmp + (size_t)s0*FD + lane*4);
            acc0.x += v0.x; acc0.y += v0.y; acc0.z += v0.z; acc0.w += v0.w;
        }
    }

    float invd = g_inv[node];
    float4 b4 = *reinterpret_cast<const float4*>(bias + lane*4);
    float4 h;
    h.x = fmaxf(fmaf(acc0.x + acc1.x, invd, b4.x), 0.f);
    h.y = fmaxf(fmaf(acc0.y + acc1.y, invd, b4.y), 0.f);
    h.z = fmaxf(fmaf(acc0.z + acc1.z, invd, b4.z), 0.f);
    h.w = fmaxf(fmaf(acc0.w + acc1.w, invd, b4.w), 0.f);
    *reinterpret_cast<float4*>(H + (size_t)node*FD + lane*4) = h;
}

// ---------------- pooling + final ----------------

__global__ void k_pool() {
    int b = blockIdx.x >> 3;
    int q = blockIdx.x & 7;
    int d = threadIdx.x;
    const float* base = g_h2 + ((size_t)(b*PP + q*(PP/8)))*FD + d;
    float s = 0.f;
    #pragma unroll 4
    for (int n = 0; n < PP/8; n++) s += base[(size_t)n*FD];
    g_part[blockIdx.x*FD + d] = s;
}

__global__ void k_final(const float* __restrict__ Wl, const float* __restrict__ bl,
                        float* __restrict__ out) {
    int t = threadIdx.x;
    if (t >= BB*CC) return;
    int b = t / CC, c = t % CC;
    float s = 0.f;
    for (int d = 0; d < FD; d++) {
        float p = 0.f;
        #pragma unroll
        for (int q = 0; q < 8; q++) p += g_part[(b*8 + q)*FD + d];
        s = fmaf(p, Wl[d*CC + c], s);
    }
    out[t] = fmaf(s, KINV, bl[c]);
}

// ---------------- launch ----------------

extern "C" void kernel_launch(void* const* d_in, const int* in_sizes, int n_in,
                              void* d_out, int out_size) {
    const float* x  = (const float*)d_in[0];
    const int*   ei = (const int*)  d_in[1];
    const float* W1 = (const float*)d_in[3];
    const float* b1 = (const float*)d_in[4];
    const float* W2 = (const float*)d_in[5];
    const float* b2 = (const float*)d_in[6];
    // d_in[7]=Wa, d_in[8]=ba dead (softmax rows sum to 1); d_in[2]=batch implied
    const float* Wl = (const float*)d_in[9];
    const float* bl = (const float*)d_in[10];
    float* out = (float*)d_out;

    const int E = in_sizes[1] / 2;

    k_zero      <<<NBLK, 256>>>();
    k_hist      <<<(E + 511)/512, 512>>>(ei, E);
    k_scan_block<<<NBLK, 256>>>();
    k_scan_top  <<<1, 512>>>();
    k_scan_add  <<<NBLK, 256>>>();
    k_fill      <<<(E + 511)/512, 512>>>(ei, E);

    const int gemm_grid   = (NN + 127)/128;
    const int gather_grid = (NN + 7)/8;

    k_gemm_tc<1><<<gemm_grid, 256>>>(x, W1);
    k_gather<1> <<<gather_grid, 256>>>(b1);

    k_gemm_tc<2><<<gemm_grid, 256>>>(x /*unused*/, W2);
    k_gather<2> <<<gather_grid, 256>>>(b2);

    k_pool <<<BB*8, FD>>>();
    k_final<<<1, 512>>>(Wl, bl, out);
}